// round 10
// baseline (speedup 1.0000x reference)
#include <cuda_runtime.h>
#include <cuda_bf16.h>
#include <stdint.h>

#define HID   1024
#define NSEQ  1024
#define DHEAD 64

__device__ float g_q[NSEQ * HID];
__device__ float g_k[NSEQ * HID];
__device__ float g_v[NSEQ * HID];
__device__ float g_pk[2048 * HID];
__device__ float g_pq[2048 * HID];
__device__ __nv_bfloat16 g_scores[16 * NSEQ * NSEQ];  // exp(S) in bf16
__device__ float g_psum[16 * NSEQ * 16];
__device__ float g_rinv[16 * NSEQ];
__device__ float g_ctx[NSEQ * HID];
__device__ float g_proj[NSEQ * HID];

__device__ __forceinline__ uint32_t f2bf2(float lo, float hi) {
    uint32_t r;
    asm("cvt.rn.bf16x2.f32 %0, %1, %2;" : "=r"(r) : "f"(hi), "f"(lo));
    return r;
}
__device__ __forceinline__ void mma16(float* c, const uint32_t* a, const uint32_t* b) {
    asm volatile(
        "mma.sync.aligned.m16n8k16.row.col.f32.bf16.bf16.f32 "
        "{%0,%1,%2,%3}, {%4,%5,%6,%7}, {%8,%9}, {%0,%1,%2,%3};\n"
        : "+f"(c[0]), "+f"(c[1]), "+f"(c[2]), "+f"(c[3])
        : "r"(a[0]), "r"(a[1]), "r"(a[2]), "r"(a[3]), "r"(b[0]), "r"(b[1]));
}
__device__ __forceinline__ void ldsm4(uint32_t* r, uint32_t addr) {
    asm volatile("ldmatrix.sync.aligned.m8n8.x4.shared.b16 {%0,%1,%2,%3}, [%4];\n"
        : "=r"(r[0]), "=r"(r[1]), "=r"(r[2]), "=r"(r[3]) : "r"(addr));
}
__device__ __forceinline__ uint32_t smem_u32(const void* p) {
    return (uint32_t)__cvta_generic_to_shared(p);
}

#define ASTRIDE 40

// ============== bf16 NT GEMM (unchanged, proven) ==============
__global__ __launch_bounds__(256)
void gemm_bf16(const float* __restrict__ A,
               const float* __restrict__ W0, const float* __restrict__ b0, float* __restrict__ C0,
               const float* __restrict__ W1, const float* __restrict__ b1, float* __restrict__ C1,
               const float* __restrict__ W2, const float* __restrict__ b2, float* __restrict__ C2)
{
    __shared__ __nv_bfloat16 As[2][128 * ASTRIDE];
    __shared__ __nv_bfloat16 Ws[2][128 * ASTRIDE];

    const int z = blockIdx.z;
    const float* W    = (z == 0) ? W0 : ((z == 1) ? W1 : W2);
    const float* bias = (z == 0) ? b0 : ((z == 1) ? b1 : b2);
    float*       C    = (z == 0) ? C0 : ((z == 1) ? C1 : C2);

    const int m0 = blockIdx.y * 128, n0 = blockIdx.x * 128;
    const int t = threadIdx.x, lane = t & 31, warp = t >> 5;
    const int g = lane >> 2, qd = lane & 3;
    const int wm = warp >> 2, wn = warp & 3;
    const int lr7 = lane & 7;

    const uint32_t aoff = ((uint32_t)((wm * 64 + lr7 + ((lane >> 3) & 1) * 8) * ASTRIDE
                          + (lane >> 4) * 8)) * 2;
    const uint32_t boff = ((uint32_t)((wn * 32 + lr7 + (lane >> 4) * 8) * ASTRIDE
                          + ((lane >> 3) & 1) * 8)) * 2;
    const uint32_t asb = smem_u32(As[0]);
    const uint32_t wsb = smem_u32(Ws[0]);
    const uint32_t bufstep = 128 * ASTRIDE * 2;

    const int lrow = t >> 1, lkoff = (t & 1) * 16;
    const float* Ap = A + (size_t)(m0 + lrow) * HID + lkoff;
    const float* Wp = W + (size_t)(n0 + lrow) * HID + lkoff;

    {
        uint32_t pa[8], pw[8];
#pragma unroll
        for (int f = 0; f < 4; f++) {
            float4 va = *(const float4*)(Ap + f * 4);
            float4 vw = *(const float4*)(Wp + f * 4);
            pa[f*2] = f2bf2(va.x, va.y); pa[f*2+1] = f2bf2(va.z, va.w);
            pw[f*2] = f2bf2(vw.x, vw.y); pw[f*2+1] = f2bf2(vw.z, vw.w);
        }
        uint32_t* da = (uint32_t*)&As[0][lrow * ASTRIDE + lkoff];
        uint32_t* dw = (uint32_t*)&Ws[0][lrow * ASTRIDE + lkoff];
        *(uint4*)da = make_uint4(pa[0], pa[1], pa[2], pa[3]);
        *(uint4*)(da + 4) = make_uint4(pa[4], pa[5], pa[6], pa[7]);
        *(uint4*)dw = make_uint4(pw[0], pw[1], pw[2], pw[3]);
        *(uint4*)(dw + 4) = make_uint4(pw[4], pw[5], pw[6], pw[7]);
    }
    __syncthreads();

    float acc[4][4][4];
#pragma unroll
    for (int i = 0; i < 4; i++)
#pragma unroll
        for (int j = 0; j < 4; j++)
#pragma unroll
            for (int e = 0; e < 4; e++) acc[i][j][e] = 0.0f;

    for (int kt = 0; kt < 32; kt++) {
        const int cur = kt & 1;
        float4 pa4[4], pw4[4];
        const bool more = (kt + 1 < 32);
        if (more) {
#pragma unroll
            for (int f = 0; f < 4; f++) {
                pa4[f] = *(const float4*)(Ap + (kt + 1) * 32 + f * 4);
                pw4[f] = *(const float4*)(Wp + (kt + 1) * 32 + f * 4);
            }
        }
        const uint32_t Abase = asb + cur * bufstep + aoff;
        const uint32_t Bbase = wsb + cur * bufstep + boff;
#pragma unroll
        for (int kk = 0; kk < 2; kk++) {
            uint32_t af[4][4], bf[4][2];
#pragma unroll
            for (int tm = 0; tm < 4; tm++)
                ldsm4(af[tm], Abase + tm * 16 * ASTRIDE * 2 + kk * 32);
#pragma unroll
            for (int tnp = 0; tnp < 2; tnp++) {
                uint32_t bb[4];
                ldsm4(bb, Bbase + tnp * 16 * ASTRIDE * 2 + kk * 32);
                bf[2*tnp][0] = bb[0]; bf[2*tnp][1] = bb[1];
                bf[2*tnp+1][0] = bb[2]; bf[2*tnp+1][1] = bb[3];
            }
#pragma unroll
            for (int tm = 0; tm < 4; tm++)
#pragma unroll
                for (int tn = 0; tn < 4; tn++) mma16(acc[tm][tn], af[tm], bf[tn]);
        }
        if (more) {
            const int nx = cur ^ 1;
            uint32_t qa[8], qw[8];
#pragma unroll
            for (int f = 0; f < 4; f++) {
                qa[f*2] = f2bf2(pa4[f].x, pa4[f].y); qa[f*2+1] = f2bf2(pa4[f].z, pa4[f].w);
                qw[f*2] = f2bf2(pw4[f].x, pw4[f].y); qw[f*2+1] = f2bf2(pw4[f].z, pw4[f].w);
            }
            uint32_t* da = (uint32_t*)&As[nx][lrow * ASTRIDE + lkoff];
            uint32_t* dw = (uint32_t*)&Ws[nx][lrow * ASTRIDE + lkoff];
            *(uint4*)da = make_uint4(qa[0], qa[1], qa[2], qa[3]);
            *(uint4*)(da + 4) = make_uint4(qa[4], qa[5], qa[6], qa[7]);
            *(uint4*)dw = make_uint4(qw[0], qw[1], qw[2], qw[3]);
            *(uint4*)(dw + 4) = make_uint4(qw[4], qw[5], qw[6], qw[7]);
            __syncthreads();
        }
    }

#pragma unroll
    for (int tm = 0; tm < 4; tm++)
#pragma unroll
        for (int tn = 0; tn < 4; tn++) {
            const int row = m0 + wm * 64 + tm * 16 + g;
            const int col = n0 + wn * 32 + tn * 8 + 2 * qd;
            const float bv0 = bias[col], bv1 = bias[col + 1];
            *(float2*)&C[(size_t)row * HID + col] =
                make_float2(acc[tm][tn][0] + bv0, acc[tm][tn][1] + bv1);
            *(float2*)&C[(size_t)(row + 8) * HID + col] =
                make_float2(acc[tm][tn][2] + bv0, acc[tm][tn][3] + bv1);
        }
}

#define QSTR 72

// ===== score v3: 128i x 64j tile, 256 thr, 88KB smem -> 2 CTAs/SM =====
// S = qk + gather(G1=q×pk_band) + gather(G2=k×pq_band); band rows b=i-j+63 in [0,191)
__global__ __launch_bounds__(256, 2)
void score_mma()
{
    extern __shared__ char smraw[];
    __nv_bfloat16* qS = (__nv_bfloat16*)smraw;        // [128][72]
    __nv_bfloat16* kS = qS + 128 * QSTR;              // [64][72]
    __nv_bfloat16* bS = kS + 64 * QSTR;               // [192][72]
    float*         Gs = (float*)(bS + 192 * QSTR);    // [128][68]

    const int h = blockIdx.z, i0 = blockIdx.y * 128, j0 = blockIdx.x * 64;
    const int t = threadIdx.x, lane = t & 31, warp = t >> 5;
    const int g = lane >> 2, qd = lane & 3;
    const int wm = warp & 3, wn = warp >> 2;   // wm: 4 (i/rows), wn: 2 (j/cols)
    const int lr7 = lane & 7;

    const uint32_t aoffQ  = ((uint32_t)((wm*32 + lr7 + ((lane>>3)&1)*8) * QSTR + (lane>>4)*8)) * 2;
    const uint32_t aoffK2 = ((uint32_t)((wm*16 + lr7 + ((lane>>3)&1)*8) * QSTR + (lane>>4)*8)) * 2;
    const uint32_t boffN  = ((uint32_t)((wn*32 + lr7 + (lane>>4)*8) * QSTR + ((lane>>3)&1)*8)) * 2;
    const uint32_t qSb = smem_u32(qS), kSb = smem_u32(kS), bSb = smem_u32(bS);

    const int dbase = 1024 + i0 - j0 - 63;   // band source row for blocal=0

    // stage qS: 128 rows x 64
    {
        const int lrow = t >> 1, dh = (t & 1) * 32;
        const float* qp = g_q + (size_t)(i0 + lrow) * HID + h * DHEAD + dh;
        uint32_t u[16];
#pragma unroll
        for (int f = 0; f < 8; f++) {
            float4 a = *(const float4*)(qp + f * 4);
            u[f*2] = f2bf2(a.x, a.y); u[f*2+1] = f2bf2(a.z, a.w);
        }
        uint32_t* d = (uint32_t*)&qS[lrow * QSTR + dh];
#pragma unroll
        for (int f = 0; f < 4; f++)
            *(uint4*)(d + f * 4) = make_uint4(u[f*4], u[f*4+1], u[f*4+2], u[f*4+3]);
    }
    // stage kS: 64 rows x 64
    {
        const int lrow = t >> 2, dh = (t & 3) * 16;
        const float* kp = g_k + (size_t)(j0 + lrow) * HID + h * DHEAD + dh;
        uint32_t u[8];
#pragma unroll
        for (int f = 0; f < 4; f++) {
            float4 a = *(const float4*)(kp + f * 4);
            u[f*2] = f2bf2(a.x, a.y); u[f*2+1] = f2bf2(a.z, a.w);
        }
        uint32_t* d = (uint32_t*)&kS[lrow * QSTR + dh];
        *(uint4*)d = make_uint4(u[0], u[1], u[2], u[3]);
        *(uint4*)(d + 4) = make_uint4(u[4], u[5], u[6], u[7]);
    }
    // stage bS (pk): 192 rows x 64 (rows >190 clamped; never gathered)
#pragma unroll
    for (int rr = 0; rr < 3; rr++) {
        const int row = rr * 64 + (t >> 2);
        const int src = (row < 191) ? row : 190;
        const int dh = (t & 3) * 16;
        const float* bp = g_pk + (size_t)(dbase + src) * HID + h * DHEAD + dh;
        uint32_t u[8];
#pragma unroll
        for (int f = 0; f < 4; f++) {
            float4 a = *(const float4*)(bp + f * 4);
            u[f*2] = f2bf2(a.x, a.y); u[f*2+1] = f2bf2(a.z, a.w);
        }
        uint32_t* d = (uint32_t*)&bS[row * QSTR + dh];
        *(uint4*)d = make_uint4(u[0], u[1], u[2], u[3]);
        *(uint4*)(d + 4) = make_uint4(u[4], u[5], u[6], u[7]);
    }
    __syncthreads();

    float S[2][4][4];
#pragma unroll
    for (int i = 0; i < 2; i++)
#pragma unroll
        for (int j = 0; j < 4; j++)
#pragma unroll
            for (int e = 0; e < 4; e++) S[i][j][e] = 0.0f;

    // QK: S[128][64]
#pragma unroll
    for (int kk = 0; kk < 4; kk++) {
        uint32_t af[2][4], bf[4][2];
#pragma unroll
        for (int tm = 0; tm < 2; tm++)
            ldsm4(af[tm], qSb + aoffQ + tm * 16 * QSTR * 2 + kk * 32);
#pragma unroll
        for (int tnp = 0; tnp < 2; tnp++) {
            uint32_t bb[4];
            ldsm4(bb, kSb + boffN + tnp * 16 * QSTR * 2 + kk * 32);
            bf[2*tnp][0] = bb[0]; bf[2*tnp][1] = bb[1];
            bf[2*tnp+1][0] = bb[2]; bf[2*tnp+1][1] = bb[3];
        }
#pragma unroll
        for (int tm = 0; tm < 2; tm++)
#pragma unroll
            for (int tn = 0; tn < 4; tn++) mma16(S[tm][tn], af[tm], bf[tn]);
    }

    // band passes
    for (int pass = 0; pass < 2; pass++) {
        if (pass == 1) {
            __syncthreads();   // all bS reads from pass 0 done (gather syncs cover, but be safe)
#pragma unroll
            for (int rr = 0; rr < 3; rr++) {
                const int row = rr * 64 + (t >> 2);
                const int src = (row < 191) ? row : 190;
                const int dh = (t & 3) * 16;
                const float* bp = g_pq + (size_t)(dbase + src) * HID + h * DHEAD + dh;
                uint32_t u[8];
#pragma unroll
                for (int f = 0; f < 4; f++) {
                    float4 a = *(const float4*)(bp + f * 4);
                    u[f*2] = f2bf2(a.x, a.y); u[f*2+1] = f2bf2(a.z, a.w);
                }
                uint32_t* d = (uint32_t*)&bS[row * QSTR + dh];
                *(uint4*)d = make_uint4(u[0], u[1], u[2], u[3]);
                *(uint4*)(d + 4) = make_uint4(u[4], u[5], u[6], u[7]);
            }
            __syncthreads();
        }
        for (int qh = 0; qh < 3; qh++) {
            const uint32_t Bq = bSb + boffN + qh * 64 * QSTR * 2;
            if (pass == 0) {
                // G1[i][b] = q x pk_band quarter: [128][64]
                float Ga[2][4][4];
#pragma unroll
                for (int i = 0; i < 2; i++)
#pragma unroll
                    for (int j = 0; j < 4; j++)
#pragma unroll
                        for (int e = 0; e < 4; e++) Ga[i][j][e] = 0.0f;
#pragma unroll
                for (int kk = 0; kk < 4; kk++) {
                    uint32_t af[2][4], bf[4][2];
#pragma unroll
                    for (int tm = 0; tm < 2; tm++)
                        ldsm4(af[tm], qSb + aoffQ + tm * 16 * QSTR * 2 + kk * 32);
#pragma unroll
                    for (int tnp = 0; tnp < 2; tnp++) {
                        uint32_t bb[4];
                        ldsm4(bb, Bq + tnp * 16 * QSTR * 2 + kk * 32);
                        bf[2*tnp][0] = bb[0]; bf[2*tnp][1] = bb[1];
                        bf[2*tnp+1][0] = bb[2]; bf[2*tnp+1][1] = bb[3];
                    }
#pragma unroll
                    for (int tm = 0; tm < 2; tm++)
#pragma unroll
                        for (int tn = 0; tn < 4; tn++) mma16(Ga[tm][tn], af[tm], bf[tn]);
                }
#pragma unroll
                for (int tm = 0; tm < 2; tm++)
#pragma unroll
                    for (int tn = 0; tn < 4; tn++) {
                        const int r = wm * 32 + tm * 16 + g;
                        const int c = wn * 32 + tn * 8 + 2 * qd;
                        *(float2*)&Gs[r * 68 + c] = make_float2(Ga[tm][tn][0], Ga[tm][tn][1]);
                        *(float2*)&Gs[(r + 8) * 68 + c] = make_float2(Ga[tm][tn][2], Ga[tm][tn][3]);
                    }
            } else {
                // G2[j][b] = k x pq_band quarter: [64][64]
                float Ga[4][4];
#pragma unroll
                for (int j = 0; j < 4; j++)
#pragma unroll
                    for (int e = 0; e < 4; e++) Ga[j][e] = 0.0f;
#pragma unroll
                for (int kk = 0; kk < 4; kk++) {
                    uint32_t af[4], bf[4][2];
                    ldsm4(af, kSb + aoffK2 + kk * 32);
#pragma unroll
                    for (int tnp = 0; tnp < 2; tnp++) {
                        uint32_t bb[4];
                        ldsm4(bb, Bq + tnp * 16 * QSTR * 2 + kk * 32);
                        bf[2*tnp][0] = bb[0]; bf[2*tnp][1] = bb[1];
                        bf[2*tnp+1][0] = bb[2]; bf[2*tnp+1][1] = bb[3];
                    }
#pragma unroll
                    for (int tn = 0; tn < 4; tn++) mma16(Ga[tn], af, bf[tn]);
                }
#pragma unroll
                for (int tn = 0; tn < 4; tn++) {
                    const int r = wm * 16 + g;
                    const int c = wn * 32 + tn * 8 + 2 * qd;
                    *(float2*)&Gs[r * 68 + c] = make_float2(Ga[tn][0], Ga[tn][1]);
                    *(float2*)&Gs[(r + 8) * 68 + c] = make_float2(Ga[tn][2], Ga[tn][3]);
                }
            }
            __syncthreads();
            // gather
#pragma unroll
            for (int tm = 0; tm < 2; tm++)
#pragma unroll
                for (int tn = 0; tn < 4; tn++) {
                    const int il = wm * 32 + tm * 16 + g;
                    const int jl = wn * 32 + tn * 8 + 2 * qd;
                    const int b0 = il - jl + 63 - qh * 64;
                    const int bv[4] = {b0, b0 - 1, b0 + 8, b0 + 7};
                    int rv[4];
                    if (pass == 0) { rv[0] = il; rv[1] = il; rv[2] = il + 8; rv[3] = il + 8; }
                    else           { rv[0] = jl; rv[1] = jl + 1; rv[2] = jl; rv[3] = jl + 1; }
#pragma unroll
                    for (int e = 0; e < 4; e++)
                        if ((unsigned)bv[e] < 64u)
                            S[tm][tn][e] += Gs[rv[e] * 68 + bv[e]];
                }
            __syncthreads();
        }
    }

    // epilogue: exp -> bf16 store + partial row sums
    const float inv = 0.07216878364870322992f;
    float rs[2][2];
#pragma unroll
    for (int tm = 0; tm < 2; tm++) {
        float s0 = 0.0f, s1 = 0.0f;
        const int row = i0 + wm * 32 + tm * 16 + g;
        const int colb = j0 + wn * 32 + 2 * qd;
#pragma unroll
        for (int tn = 0; tn < 4; tn++) {
            float e0 = __expf(S[tm][tn][0] * inv);
            float e1 = __expf(S[tm][tn][1] * inv);
            float e2 = __expf(S[tm][tn][2] * inv);
            float e3 = __expf(S[tm][tn][3] * inv);
            s0 += e0 + e1; s1 += e2 + e3;
            *(uint32_t*)&g_scores[((size_t)h * NSEQ + row) * NSEQ + colb + tn * 8] = f2bf2(e0, e1);
            *(uint32_t*)&g_scores[((size_t)h * NSEQ + row + 8) * NSEQ + colb + tn * 8] = f2bf2(e2, e3);
        }
        rs[tm][0] = s0; rs[tm][1] = s1;
    }
#pragma unroll
    for (int tm = 0; tm < 2; tm++) {
        float s0 = rs[tm][0], s1 = rs[tm][1];
        s0 += __shfl_xor_sync(0xffffffffu, s0, 1);
        s0 += __shfl_xor_sync(0xffffffffu, s0, 2);
        s1 += __shfl_xor_sync(0xffffffffu, s1, 1);
        s1 += __shfl_xor_sync(0xffffffffu, s1, 2);
        if (qd == 0) {
            const int r = wm * 32 + tm * 16 + g;
            Gs[r * 2 + wn] = s0;
            Gs[(r + 8) * 2 + wn] = s1;
        }
    }
    __syncthreads();
    if (t < 128) {
        float tot = Gs[t * 2] + Gs[t * 2 + 1];
        g_psum[((size_t)(h << 10) + i0 + t) * 16 + blockIdx.x] = tot;
    }
}

// ============== rinv: 1/rowsum (16 partials) ==============
__global__ __launch_bounds__(256)
void rinv_kernel()
{
    const int i = blockIdx.x * 256 + threadIdx.x;
    const float* pp = g_psum + (size_t)i * 16;
    float s = 0.0f;
#pragma unroll
    for (int f = 0; f < 4; f++) {
        float4 a = *(const float4*)(pp + f * 4);
        s += a.x + a.y + a.z + a.w;
    }
    g_rinv[i] = 1.0f / s;
}

#define PSTRIDE 40

// ====== AV (unchanged from R9, proven) ======
__global__ __launch_bounds__(256)
void av_mma()
{
    __shared__ __nv_bfloat16 Ps[128 * PSTRIDE];
    __shared__ __nv_bfloat16 Vt[64 * PSTRIDE];
    const int h = blockIdx.y, i0 = blockIdx.x * 128;
    const int t = threadIdx.x, lane = t & 31, warp = t >> 5;
    const int g = lane >> 2, qd = lane & 3;
    const int wm = warp >> 2, wn = warp & 3;
    const int lr7 = lane & 7;

    const uint32_t aoffP = ((uint32_t)((wm * 64 + lr7 + ((lane >> 3) & 1) * 8) * PSTRIDE
                           + (lane >> 4) * 8)) * 2;
    const uint32_t boffV = ((uint32_t)((wn * 16 + lr7 + (lane >> 4) * 8) * PSTRIDE
                           + ((lane >> 3) & 1) * 8)) * 2;
    const uint32_t PsB = smem_u32(Ps), VtB = smem_u32(Vt);

    const int lrow = t >> 1, lj = (t & 1) * 16;
    const __nv_bfloat16* sp = g_scores + ((size_t)h * NSEQ + i0 + lrow) * NSEQ + lj;

    float rv[4][2];
#pragma unroll
    for (int tm = 0; tm < 4; tm++) {
        const int rl = wm * 64 + tm * 16 + g;
        rv[tm][0] = g_rinv[h * NSEQ + i0 + rl];
        rv[tm][1] = g_rinv[h * NSEQ + i0 + rl + 8];
    }

    float acc[4][2][4];
#pragma unroll
    for (int i = 0; i < 4; i++)
#pragma unroll
        for (int j = 0; j < 2; j++)
#pragma unroll
            for (int e = 0; e < 4; e++) acc[i][j][e] = 0.0f;

    for (int jt = 0; jt < NSEQ; jt += 32) {
        __syncthreads();
        {
            uint4 u0 = *(const uint4*)(sp + jt);
            uint4 u1 = *(const uint4*)(sp + jt + 8);
            *(uint4*)&Ps[lrow * PSTRIDE + lj] = u0;
            *(uint4*)&Ps[lrow * PSTRIDE + lj + 8] = u1;
        }
        {
            const int vr = t >> 3, dblk = (t & 7) * 8;
            const float* vp = g_v + (size_t)(jt + vr) * HID + h * DHEAD + dblk;
            float4 a = *(const float4*)vp;
            float4 b = *(const float4*)(vp + 4);
            Vt[(dblk + 0) * PSTRIDE + vr] = __float2bfloat16(a.x);
            Vt[(dblk + 1) * PSTRIDE + vr] = __float2bfloat16(a.y);
            Vt[(dblk + 2) * PSTRIDE + vr] = __float2bfloat16(a.z);
            Vt[(dblk + 3) * PSTRIDE + vr] = __float2bfloat16(a.w);
            Vt[(dblk + 4) * PSTRIDE + vr] = __float2bfloat16(b.x);
            Vt[(dblk + 5) * PSTRIDE + vr] = __float2bfloat16(b.y);
            Vt[(dblk + 6) * PSTRIDE + vr] = __float2bfloat16(b.z);
            Vt[(dblk + 7) * PSTRIDE + vr] = __float2bfloat16(b.w);
        }
        __syncthreads();
#pragma unroll
        for (int kk = 0; kk < 2; kk++) {
            uint32_t af[4][4], bf[2][2];
#pragma unroll
            for (int tm = 0; tm < 4; tm++)
                ldsm4(af[tm], PsB + aoffP + tm * 16 * PSTRIDE * 2 + kk * 32);
            {
                uint32_t bb[4];
                ldsm4(bb, VtB + boffV + kk * 32);
                bf[0][0] = bb[0]; bf[0][1] = bb[1];
                bf[1][0] = bb[2]; bf[1][1] = bb[3];
            }
#pragma unroll
            for (int tm = 0; tm < 4; tm++)
#pragma unroll
                for (int tn = 0; tn < 2; tn++) mma16(acc[tm][tn], af[tm], bf[tn]);
        }
    }
#pragma unroll
    for (int tm = 0; tm < 4; tm++)
#pragma unroll
        for (int tn = 0; tn < 2; tn++) {
            const int row = i0 + wm * 64 + tm * 16 + g;
            const int col = h * DHEAD + wn * 16 + tn * 8 + 2 * qd;
            *(float2*)&g_ctx[(size_t)row * HID + col] =
                make_float2(acc[tm][tn][0] * rv[tm][0], acc[tm][tn][1] * rv[tm][0]);
            *(float2*)&g_ctx[(size_t)(row + 8) * HID + col] =
                make_float2(acc[tm][tn][2] * rv[tm][1], acc[tm][tn][3] * rv[tm][1]);
        }
}

// ============== residual + LayerNorm =========================================
__global__ __launch_bounds__(256)
void ln_kernel(const float* __restrict__ hs, const float* __restrict__ gg,
               const float* __restrict__ bb, float* __restrict__ out)
{
    const int row = blockIdx.x, t = threadIdx.x;
    __shared__ float red[8];
    float4 p = *(const float4*)(g_proj + (size_t)row * HID + t * 4);
    float4 hv = *(const float4*)(hs + (size_t)row * HID + t * 4);
    float x0 = p.x+hv.x, x1 = p.y+hv.y, x2 = p.z+hv.z, x3 = p.w+hv.w;
    float s = x0+x1+x2+x3;
#pragma unroll
    for (int o = 16; o > 0; o >>= 1) s += __shfl_xor_sync(0xffffffffu, s, o);
    if ((t & 31) == 0) red[t >> 5] = s;
    __syncthreads();
    float mu = (red[0]+red[1]+red[2]+red[3]+red[4]+red[5]+red[6]+red[7]) * (1.0f/1024.0f);
    float d0 = x0-mu, d1 = x1-mu, d2 = x2-mu, d3 = x3-mu;
    float sq = d0*d0 + d1*d1 + d2*d2 + d3*d3;
#pragma unroll
    for (int o = 16; o > 0; o >>= 1) sq += __shfl_xor_sync(0xffffffffu, sq, o);
    __syncthreads();
    if ((t & 31) == 0) red[t >> 5] = sq;
    __syncthreads();
    float var = (red[0]+red[1]+red[2]+red[3]+red[4]+red[5]+red[6]+red[7]) * (1.0f/1024.0f);
    float rstd = rsqrtf(var + 1e-7f);
    float4 g4 = *(const float4*)(gg + t * 4);
    float4 b4 = *(const float4*)(bb + t * 4);
    *(float4*)(out + (size_t)row * HID + t * 4) =
        make_float4(d0*rstd*g4.x + b4.x, d1*rstd*g4.y + b4.y,
                    d2*rstd*g4.z + b4.z, d3*rstd*g4.w + b4.w);
}

extern "C" void kernel_launch(void* const* d_in, const int* in_sizes, int n_in,
                              void* d_out, int out_size)
{
    const float* hs  = (const float*)d_in[0];
    const float* rel = (const float*)d_in[1];
    const float* Wq  = (const float*)d_in[2];  const float* bq  = (const float*)d_in[3];
    const float* Wk  = (const float*)d_in[4];  const float* bk  = (const float*)d_in[5];
    const float* Wv  = (const float*)d_in[6];  const float* bv  = (const float*)d_in[7];
    const float* Wpk = (const float*)d_in[8];  const float* bpk = (const float*)d_in[9];
    const float* Wpq = (const float*)d_in[10]; const float* bpq = (const float*)d_in[11];
    const float* Wo  = (const float*)d_in[12]; const float* bo  = (const float*)d_in[13];
    const float* lng = (const float*)d_in[14]; const float* lnb = (const float*)d_in[15];

    float *q_, *k_, *v_, *pk_, *pq_, *ctx_, *proj_;
    cudaGetSymbolAddress((void**)&q_, g_q);
    cudaGetSymbolAddress((void**)&k_, g_k);
    cudaGetSymbolAddress((void**)&v_, g_v);
    cudaGetSymbolAddress((void**)&pk_, g_pk);
    cudaGetSymbolAddress((void**)&pq_, g_pq);
    cudaGetSymbolAddress((void**)&ctx_, g_ctx);
    cudaGetSymbolAddress((void**)&proj_, g_proj);

    // smem: qS(128*72) + kS(64*72) + bS(192*72) bf16 + Gs(128*68) f32 = 88 KB
    const int score_smem = (128 * QSTR + 64 * QSTR + 192 * QSTR) * 2 + 128 * 68 * 4;
    cudaFuncSetAttribute(score_mma, cudaFuncAttributeMaxDynamicSharedMemorySize, score_smem);

    gemm_bf16<<<dim3(8, 8, 3), 256>>>(hs, Wq, bq, q_, Wk, bk, k_, Wv, bv, v_);
    gemm_bf16<<<dim3(8, 16, 2), 256>>>(rel, Wpk, bpk, pk_, Wpq, bpq, pq_, Wpq, bpq, pq_);
    score_mma<<<dim3(16, 8, 16), 256, score_smem>>>();
    rinv_kernel<<<64, 256>>>();
    av_mma<<<dim3(8, 16), 256>>>();
    gemm_bf16<<<dim3(8, 8, 1), 256>>>(ctx_, Wo, bo, proj_, Wo, bo, proj_, Wo, bo, proj_);
    ln_kernel<<<1024, 256>>>(hs, lng, lnb, (float*)d_out);
}

// round 11
// speedup vs baseline: 1.1079x; 1.1079x over previous
#include <cuda_runtime.h>
#include <cuda_bf16.h>
#include <stdint.h>

#define HID   1024
#define NSEQ  1024
#define DHEAD 64

__device__ float g_q[NSEQ * HID];
__device__ float g_k[NSEQ * HID];
__device__ float g_v[NSEQ * HID];
__device__ float g_pk[2048 * HID];
__device__ float g_pq[2048 * HID];
__device__ float g_ctx[NSEQ * HID];
__device__ float g_proj[NSEQ * HID];

__device__ __forceinline__ uint32_t f2bf2(float lo, float hi) {
    uint32_t r;
    asm("cvt.rn.bf16x2.f32 %0, %1, %2;" : "=r"(r) : "f"(hi), "f"(lo));
    return r;
}
__device__ __forceinline__ void mma16(float* c, const uint32_t* a, const uint32_t* b) {
    asm volatile(
        "mma.sync.aligned.m16n8k16.row.col.f32.bf16.bf16.f32 "
        "{%0,%1,%2,%3}, {%4,%5,%6,%7}, {%8,%9}, {%0,%1,%2,%3};\n"
        : "+f"(c[0]), "+f"(c[1]), "+f"(c[2]), "+f"(c[3])
        : "r"(a[0]), "r"(a[1]), "r"(a[2]), "r"(a[3]), "r"(b[0]), "r"(b[1]));
}
__device__ __forceinline__ void ldsm4(uint32_t* r, uint32_t addr) {
    asm volatile("ldmatrix.sync.aligned.m8n8.x4.shared.b16 {%0,%1,%2,%3}, [%4];\n"
        : "=r"(r[0]), "=r"(r[1]), "=r"(r[2]), "=r"(r[3]) : "r"(addr));
}
__device__ __forceinline__ uint32_t smem_u32(const void* p) {
    return (uint32_t)__cvta_generic_to_shared(p);
}

#define ASTRIDE 40

// ============== bf16 NT GEMM (unchanged, proven) ==============
__global__ __launch_bounds__(256)
void gemm_bf16(const float* __restrict__ A,
               const float* __restrict__ W0, const float* __restrict__ b0, float* __restrict__ C0,
               const float* __restrict__ W1, const float* __restrict__ b1, float* __restrict__ C1,
               const float* __restrict__ W2, const float* __restrict__ b2, float* __restrict__ C2)
{
    __shared__ __nv_bfloat16 As[2][128 * ASTRIDE];
    __shared__ __nv_bfloat16 Ws[2][128 * ASTRIDE];

    const int z = blockIdx.z;
    const float* W    = (z == 0) ? W0 : ((z == 1) ? W1 : W2);
    const float* bias = (z == 0) ? b0 : ((z == 1) ? b1 : b2);
    float*       C    = (z == 0) ? C0 : ((z == 1) ? C1 : C2);

    const int m0 = blockIdx.y * 128, n0 = blockIdx.x * 128;
    const int t = threadIdx.x, lane = t & 31, warp = t >> 5;
    const int g = lane >> 2, qd = lane & 3;
    const int wm = warp >> 2, wn = warp & 3;
    const int lr7 = lane & 7;

    const uint32_t aoff = ((uint32_t)((wm * 64 + lr7 + ((lane >> 3) & 1) * 8) * ASTRIDE
                          + (lane >> 4) * 8)) * 2;
    const uint32_t boff = ((uint32_t)((wn * 32 + lr7 + (lane >> 4) * 8) * ASTRIDE
                          + ((lane >> 3) & 1) * 8)) * 2;
    const uint32_t asb = smem_u32(As[0]);
    const uint32_t wsb = smem_u32(Ws[0]);
    const uint32_t bufstep = 128 * ASTRIDE * 2;

    const int lrow = t >> 1, lkoff = (t & 1) * 16;
    const float* Ap = A + (size_t)(m0 + lrow) * HID + lkoff;
    const float* Wp = W + (size_t)(n0 + lrow) * HID + lkoff;

    {
        uint32_t pa[8], pw[8];
#pragma unroll
        for (int f = 0; f < 4; f++) {
            float4 va = *(const float4*)(Ap + f * 4);
            float4 vw = *(const float4*)(Wp + f * 4);
            pa[f*2] = f2bf2(va.x, va.y); pa[f*2+1] = f2bf2(va.z, va.w);
            pw[f*2] = f2bf2(vw.x, vw.y); pw[f*2+1] = f2bf2(vw.z, vw.w);
        }
        uint32_t* da = (uint32_t*)&As[0][lrow * ASTRIDE + lkoff];
        uint32_t* dw = (uint32_t*)&Ws[0][lrow * ASTRIDE + lkoff];
        *(uint4*)da = make_uint4(pa[0], pa[1], pa[2], pa[3]);
        *(uint4*)(da + 4) = make_uint4(pa[4], pa[5], pa[6], pa[7]);
        *(uint4*)dw = make_uint4(pw[0], pw[1], pw[2], pw[3]);
        *(uint4*)(dw + 4) = make_uint4(pw[4], pw[5], pw[6], pw[7]);
    }
    __syncthreads();

    float acc[4][4][4];
#pragma unroll
    for (int i = 0; i < 4; i++)
#pragma unroll
        for (int j = 0; j < 4; j++)
#pragma unroll
            for (int e = 0; e < 4; e++) acc[i][j][e] = 0.0f;

    for (int kt = 0; kt < 32; kt++) {
        const int cur = kt & 1;
        float4 pa4[4], pw4[4];
        const bool more = (kt + 1 < 32);
        if (more) {
#pragma unroll
            for (int f = 0; f < 4; f++) {
                pa4[f] = *(const float4*)(Ap + (kt + 1) * 32 + f * 4);
                pw4[f] = *(const float4*)(Wp + (kt + 1) * 32 + f * 4);
            }
        }
        const uint32_t Abase = asb + cur * bufstep + aoff;
        const uint32_t Bbase = wsb + cur * bufstep + boff;
#pragma unroll
        for (int kk = 0; kk < 2; kk++) {
            uint32_t af[4][4], bf[4][2];
#pragma unroll
            for (int tm = 0; tm < 4; tm++)
                ldsm4(af[tm], Abase + tm * 16 * ASTRIDE * 2 + kk * 32);
#pragma unroll
            for (int tnp = 0; tnp < 2; tnp++) {
                uint32_t bb[4];
                ldsm4(bb, Bbase + tnp * 16 * ASTRIDE * 2 + kk * 32);
                bf[2*tnp][0] = bb[0]; bf[2*tnp][1] = bb[1];
                bf[2*tnp+1][0] = bb[2]; bf[2*tnp+1][1] = bb[3];
            }
#pragma unroll
            for (int tm = 0; tm < 4; tm++)
#pragma unroll
                for (int tn = 0; tn < 4; tn++) mma16(acc[tm][tn], af[tm], bf[tn]);
        }
        if (more) {
            const int nx = cur ^ 1;
            uint32_t qa[8], qw[8];
#pragma unroll
            for (int f = 0; f < 4; f++) {
                qa[f*2] = f2bf2(pa4[f].x, pa4[f].y); qa[f*2+1] = f2bf2(pa4[f].z, pa4[f].w);
                qw[f*2] = f2bf2(pw4[f].x, pw4[f].y); qw[f*2+1] = f2bf2(pw4[f].z, pw4[f].w);
            }
            uint32_t* da = (uint32_t*)&As[nx][lrow * ASTRIDE + lkoff];
            uint32_t* dw = (uint32_t*)&Ws[nx][lrow * ASTRIDE + lkoff];
            *(uint4*)da = make_uint4(qa[0], qa[1], qa[2], qa[3]);
            *(uint4*)(da + 4) = make_uint4(qa[4], qa[5], qa[6], qa[7]);
            *(uint4*)dw = make_uint4(qw[0], qw[1], qw[2], qw[3]);
            *(uint4*)(dw + 4) = make_uint4(qw[4], qw[5], qw[6], qw[7]);
            __syncthreads();
        }
    }

#pragma unroll
    for (int tm = 0; tm < 4; tm++)
#pragma unroll
        for (int tn = 0; tn < 4; tn++) {
            const int row = m0 + wm * 64 + tm * 16 + g;
            const int col = n0 + wn * 32 + tn * 8 + 2 * qd;
            const float bv0 = bias[col], bv1 = bias[col + 1];
            *(float2*)&C[(size_t)row * HID + col] =
                make_float2(acc[tm][tn][0] + bv0, acc[tm][tn][1] + bv1);
            *(float2*)&C[(size_t)(row + 8) * HID + col] =
                make_float2(acc[tm][tn][2] + bv0, acc[tm][tn][3] + bv1);
        }
}

#define QSTR 72
#define PSTR 136   // P/V j-stride (128 + 8 pad)

// ===== fused attention: per (h, i0): scores + exp + rowsum + P@V =====
// 256 thr, 8 warps (2x4). j-loop over 8 tiles of 128.
__global__ __launch_bounds__(256, 1)
void attn_fused()
{
    extern __shared__ char smraw[];
    __nv_bfloat16* qS = (__nv_bfloat16*)smraw;            // [128][72]
    __nv_bfloat16* kS = qS + 128 * QSTR;                  // [128][72]
    __nv_bfloat16* bS = kS + 128 * QSTR;                  // [256][72]
    float*         Gs = (float*)(bS + 256 * QSTR);        // [128][132] f32
    __nv_bfloat16* Ps = (__nv_bfloat16*)Gs;               // overlay: P bf16 [128][136]
    __nv_bfloat16* Vt = (__nv_bfloat16*)(Gs + 128 * 132); // [64][136]
    float*         red = (float*)kS;                      // reuse after loop [128][4]

    const int h = blockIdx.y, i0 = blockIdx.x * 128;
    const int t = threadIdx.x, lane = t & 31, warp = t >> 5;
    const int g = lane >> 2, qd = lane & 3;
    const int wm = warp >> 2, wn = warp & 3;
    const int lr7 = lane & 7;

    const uint32_t aoffQ = ((uint32_t)((wm*64 + lr7 + ((lane>>3)&1)*8) * QSTR + (lane>>4)*8)) * 2;
    const uint32_t boffQ = ((uint32_t)((wn*32 + lr7 + (lane>>4)*8) * QSTR + ((lane>>3)&1)*8)) * 2;
    const uint32_t aoffP = ((uint32_t)((wm*64 + lr7 + ((lane>>3)&1)*8) * PSTR + (lane>>4)*8)) * 2;
    const uint32_t boffV = ((uint32_t)((wn*16 + lr7 + (lane>>4)*8) * PSTR + ((lane>>3)&1)*8)) * 2;
    const uint32_t qSb = smem_u32(qS), kSb = smem_u32(kS), bSb = smem_u32(bS);
    const uint32_t PsB = smem_u32(Ps), VtB = smem_u32(Vt);

    // stage qS once
    {
        const int lrow = t >> 1, dh = (t & 1) * 32;
        const float* qp = g_q + (size_t)(i0 + lrow) * HID + h * DHEAD + dh;
        uint32_t u[16];
#pragma unroll
        for (int f = 0; f < 8; f++) {
            float4 a = *(const float4*)(qp + f * 4);
            u[f*2] = f2bf2(a.x, a.y); u[f*2+1] = f2bf2(a.z, a.w);
        }
        uint32_t* d = (uint32_t*)&qS[lrow * QSTR + dh];
#pragma unroll
        for (int f = 0; f < 4; f++)
            *(uint4*)(d + f * 4) = make_uint4(u[f*4], u[f*4+1], u[f*4+2], u[f*4+3]);
    }

    float acc[4][2][4];
#pragma unroll
    for (int i = 0; i < 4; i++)
#pragma unroll
        for (int j = 0; j < 2; j++)
#pragma unroll
            for (int e = 0; e < 4; e++) acc[i][j][e] = 0.0f;
    float rs[4][2];
#pragma unroll
    for (int i = 0; i < 4; i++) { rs[i][0] = 0.0f; rs[i][1] = 0.0f; }

    const int brow = (t < 255) ? t : 254;
    const float inv = 0.07216878364870322992f;  // 1/sqrt(192)

    for (int j0 = 0; j0 < NSEQ; j0 += 128) {
        __syncthreads();   // protect kS/Vt/bS/Ps reuse vs previous iteration reads
        // stage kS
        {
            const int lrow = t >> 1, dh = (t & 1) * 32;
            const float* kp = g_k + (size_t)(j0 + lrow) * HID + h * DHEAD + dh;
            uint32_t u[16];
#pragma unroll
            for (int f = 0; f < 8; f++) {
                float4 a = *(const float4*)(kp + f * 4);
                u[f*2] = f2bf2(a.x, a.y); u[f*2+1] = f2bf2(a.z, a.w);
            }
            uint32_t* d = (uint32_t*)&kS[lrow * QSTR + dh];
#pragma unroll
            for (int f = 0; f < 4; f++)
                *(uint4*)(d + f * 4) = make_uint4(u[f*4], u[f*4+1], u[f*4+2], u[f*4+3]);
        }
        // stage Vt[d][j]
        {
            const int vr = t >> 1, dblk = (t & 1) * 32;
            const float* vp = g_v + (size_t)(j0 + vr) * HID + h * DHEAD + dblk;
#pragma unroll
            for (int f = 0; f < 8; f++) {
                float4 a = *(const float4*)(vp + f * 4);
                Vt[(dblk + f*4 + 0) * PSTR + vr] = __float2bfloat16(a.x);
                Vt[(dblk + f*4 + 1) * PSTR + vr] = __float2bfloat16(a.y);
                Vt[(dblk + f*4 + 2) * PSTR + vr] = __float2bfloat16(a.z);
                Vt[(dblk + f*4 + 3) * PSTR + vr] = __float2bfloat16(a.w);
            }
        }
        // stage bS = pk band
        const int dmin = 1024 + i0 - j0 - 127;
        {
            const float* bp = g_pk + (size_t)(dmin + brow) * HID + h * DHEAD;
            uint32_t ub[32];
#pragma unroll
            for (int f = 0; f < 16; f++) {
                float4 a = *(const float4*)(bp + f * 4);
                ub[f*2] = f2bf2(a.x, a.y); ub[f*2+1] = f2bf2(a.z, a.w);
            }
            uint32_t* db = (uint32_t*)&bS[brow * QSTR];
#pragma unroll
            for (int f = 0; f < 8; f++)
                *(uint4*)(db + f * 4) = make_uint4(ub[f*4], ub[f*4+1], ub[f*4+2], ub[f*4+3]);
        }
        __syncthreads();

        float S[4][4][4];
#pragma unroll
        for (int i = 0; i < 4; i++)
#pragma unroll
            for (int j = 0; j < 4; j++)
#pragma unroll
                for (int e = 0; e < 4; e++) S[i][j][e] = 0.0f;

        // QK
#pragma unroll
        for (int kk = 0; kk < 4; kk++) {
            uint32_t af[4][4], bf[4][2];
#pragma unroll
            for (int tm = 0; tm < 4; tm++)
                ldsm4(af[tm], qSb + aoffQ + tm * 16 * QSTR * 2 + kk * 32);
#pragma unroll
            for (int tnp = 0; tnp < 2; tnp++) {
                uint32_t bb[4];
                ldsm4(bb, kSb + boffQ + tnp * 16 * QSTR * 2 + kk * 32);
                bf[2*tnp][0] = bb[0]; bf[2*tnp][1] = bb[1];
                bf[2*tnp+1][0] = bb[2]; bf[2*tnp+1][1] = bb[3];
            }
#pragma unroll
            for (int tm = 0; tm < 4; tm++)
#pragma unroll
                for (int tn = 0; tn < 4; tn++) mma16(S[tm][tn], af[tm], bf[tn]);
        }

        // band passes
        for (int pass = 0; pass < 2; pass++) {
            if (pass == 1) {
                // restage bS = pq (prior bS reads complete: covered by bh1 post-store sync)
                const float* bp = g_pq + (size_t)(dmin + brow) * HID + h * DHEAD;
                uint32_t ub[32];
#pragma unroll
                for (int f = 0; f < 16; f++) {
                    float4 a = *(const float4*)(bp + f * 4);
                    ub[f*2] = f2bf2(a.x, a.y); ub[f*2+1] = f2bf2(a.z, a.w);
                }
                uint32_t* db = (uint32_t*)&bS[brow * QSTR];
#pragma unroll
                for (int f = 0; f < 8; f++)
                    *(uint4*)(db + f * 4) = make_uint4(ub[f*4], ub[f*4+1], ub[f*4+2], ub[f*4+3]);
                __syncthreads();
            }
            const uint32_t Xb = (pass == 0) ? qSb : kSb;
            for (int bh = 0; bh < 2; bh++) {
                float Ga[4][4][4];
#pragma unroll
                for (int i = 0; i < 4; i++)
#pragma unroll
                    for (int j = 0; j < 4; j++)
#pragma unroll
                        for (int e = 0; e < 4; e++) Ga[i][j][e] = 0.0f;
#pragma unroll
                for (int kk = 0; kk < 4; kk++) {
                    uint32_t af[4][4], bf[4][2];
#pragma unroll
                    for (int tm = 0; tm < 4; tm++)
                        ldsm4(af[tm], Xb + aoffQ + tm * 16 * QSTR * 2 + kk * 32);
#pragma unroll
                    for (int tnp = 0; tnp < 2; tnp++) {
                        uint32_t bb[4];
                        ldsm4(bb, bSb + boffQ + (bh * 128 + tnp * 16) * QSTR * 2 + kk * 32);
                        bf[2*tnp][0] = bb[0]; bf[2*tnp][1] = bb[1];
                        bf[2*tnp+1][0] = bb[2]; bf[2*tnp+1][1] = bb[3];
                    }
#pragma unroll
                    for (int tm = 0; tm < 4; tm++)
#pragma unroll
                        for (int tn = 0; tn < 4; tn++) mma16(Ga[tm][tn], af[tm], bf[tn]);
                }
#pragma unroll
                for (int tm = 0; tm < 4; tm++)
#pragma unroll
                    for (int tn = 0; tn < 4; tn++) {
                        const int r = wm * 64 + tm * 16 + g;
                        const int c = wn * 32 + tn * 8 + 2 * qd;
                        *(float2*)&Gs[r * 132 + c] = make_float2(Ga[tm][tn][0], Ga[tm][tn][1]);
                        *(float2*)&Gs[(r + 8) * 132 + c] = make_float2(Ga[tm][tn][2], Ga[tm][tn][3]);
                    }
                __syncthreads();
#pragma unroll
                for (int tm = 0; tm < 4; tm++)
#pragma unroll
                    for (int tn = 0; tn < 4; tn++) {
                        const int il = wm * 64 + tm * 16 + g;
                        const int jl = wn * 32 + tn * 8 + 2 * qd;
                        const int b0v = il - jl + 127 - bh * 128;
                        const int bv[4] = {b0v, b0v - 1, b0v + 8, b0v + 7};
                        int rv[4];
                        if (pass == 0) { rv[0] = il; rv[1] = il; rv[2] = il + 8; rv[3] = il + 8; }
                        else           { rv[0] = jl; rv[1] = jl + 1; rv[2] = jl; rv[3] = jl + 1; }
#pragma unroll
                        for (int e = 0; e < 4; e++)
                            if ((unsigned)bv[e] < 128u)
                                S[tm][tn][e] += Gs[rv[e] * 132 + bv[e]];
                    }
                __syncthreads();
            }
        }

        // exp -> P smem (bf16) + rowsum accumulate
#pragma unroll
        for (int tm = 0; tm < 4; tm++) {
            float s0 = 0.0f, s1 = 0.0f;
            const int r = wm * 64 + tm * 16 + g;
            const int c = wn * 32 + 2 * qd;
#pragma unroll
            for (int tn = 0; tn < 4; tn++) {
                float e0 = __expf(S[tm][tn][0] * inv);
                float e1 = __expf(S[tm][tn][1] * inv);
                float e2 = __expf(S[tm][tn][2] * inv);
                float e3 = __expf(S[tm][tn][3] * inv);
                s0 += e0 + e1; s1 += e2 + e3;
                *(uint32_t*)&Ps[r * PSTR + c + tn * 8] = f2bf2(e0, e1);
                *(uint32_t*)&Ps[(r + 8) * PSTR + c + tn * 8] = f2bf2(e2, e3);
            }
            rs[tm][0] += s0; rs[tm][1] += s1;
        }
        __syncthreads();   // P + Vt ready

        // AV: acc += P @ V^T   (K = 128 j)
#pragma unroll
        for (int kk = 0; kk < 8; kk++) {
            uint32_t af[4][4], bf[2][2];
#pragma unroll
            for (int tm = 0; tm < 4; tm++)
                ldsm4(af[tm], PsB + aoffP + tm * 16 * PSTR * 2 + kk * 32);
            {
                uint32_t bb[4];
                ldsm4(bb, VtB + boffV + kk * 32);
                bf[0][0] = bb[0]; bf[0][1] = bb[1];
                bf[1][0] = bb[2]; bf[1][1] = bb[3];
            }
#pragma unroll
            for (int tm = 0; tm < 4; tm++)
#pragma unroll
                for (int tn = 0; tn < 2; tn++) mma16(acc[tm][tn], af[tm], bf[tn]);
        }
    }

    // final: cross-warp rowsum reduce -> rinv -> scale acc -> store ctx
    __syncthreads();
#pragma unroll
    for (int tm = 0; tm < 4; tm++) {
        float s0 = rs[tm][0], s1 = rs[tm][1];
        s0 += __shfl_xor_sync(0xffffffffu, s0, 1);
        s0 += __shfl_xor_sync(0xffffffffu, s0, 2);
        s1 += __shfl_xor_sync(0xffffffffu, s1, 1);
        s1 += __shfl_xor_sync(0xffffffffu, s1, 2);
        if (qd == 0) {
            const int r = wm * 64 + tm * 16 + g;
            red[r * 4 + wn] = s0;
            red[(r + 8) * 4 + wn] = s1;
        }
    }
    __syncthreads();
    if (t < 128) {
        float s = red[t * 4] + red[t * 4 + 1] + red[t * 4 + 2] + red[t * 4 + 3];
        red[t * 4] = 1.0f / s;
    }
    __syncthreads();
#pragma unroll
    for (int tm = 0; tm < 4; tm++) {
        const int rl = wm * 64 + tm * 16 + g;
        const float ri0 = red[rl * 4];
        const float ri1 = red[(rl + 8) * 4];
#pragma unroll
        for (int tn = 0; tn < 2; tn++) {
            const int row = i0 + rl;
            const int col = h * DHEAD + wn * 16 + tn * 8 + 2 * qd;
            *(float2*)&g_ctx[(size_t)row * HID + col] =
                make_float2(acc[tm][tn][0] * ri0, acc[tm][tn][1] * ri0);
            *(float2*)&g_ctx[(size_t)(row + 8) * HID + col] =
                make_float2(acc[tm][tn][2] * ri1, acc[tm][tn][3] * ri1);
        }
    }
}

// ============== residual + LayerNorm =========================================
__global__ __launch_bounds__(256)
void ln_kernel(const float* __restrict__ hs, const float* __restrict__ gg,
               const float* __restrict__ bb, float* __restrict__ out)
{
    const int row = blockIdx.x, t = threadIdx.x;
    __shared__ float red[8];
    float4 p = *(const float4*)(g_proj + (size_t)row * HID + t * 4);
    float4 hv = *(const float4*)(hs + (size_t)row * HID + t * 4);
    float x0 = p.x+hv.x, x1 = p.y+hv.y, x2 = p.z+hv.z, x3 = p.w+hv.w;
    float s = x0+x1+x2+x3;
#pragma unroll
    for (int o = 16; o > 0; o >>= 1) s += __shfl_xor_sync(0xffffffffu, s, o);
    if ((t & 31) == 0) red[t >> 5] = s;
    __syncthreads();
    float mu = (red[0]+red[1]+red[2]+red[3]+red[4]+red[5]+red[6]+red[7]) * (1.0f/1024.0f);
    float d0 = x0-mu, d1 = x1-mu, d2 = x2-mu, d3 = x3-mu;
    float sq = d0*d0 + d1*d1 + d2*d2 + d3*d3;
#pragma unroll
    for (int o = 16; o > 0; o >>= 1) sq += __shfl_xor_sync(0xffffffffu, sq, o);
    __syncthreads();
    if ((t & 31) == 0) red[t >> 5] = sq;
    __syncthreads();
    float var = (red[0]+red[1]+red[2]+red[3]+red[4]+red[5]+red[6]+red[7]) * (1.0f/1024.0f);
    float rstd = rsqrtf(var + 1e-7f);
    float4 g4 = *(const float4*)(gg + t * 4);
    float4 b4 = *(const float4*)(bb + t * 4);
    *(float4*)(out + (size_t)row * HID + t * 4) =
        make_float4(d0*rstd*g4.x + b4.x, d1*rstd*g4.y + b4.y,
                    d2*rstd*g4.z + b4.z, d3*rstd*g4.w + b4.w);
}

extern "C" void kernel_launch(void* const* d_in, const int* in_sizes, int n_in,
                              void* d_out, int out_size)
{
    const float* hs  = (const float*)d_in[0];
    const float* rel = (const float*)d_in[1];
    const float* Wq  = (const float*)d_in[2];  const float* bq  = (const float*)d_in[3];
    const float* Wk  = (const float*)d_in[4];  const float* bk  = (const float*)d_in[5];
    const float* Wv  = (const float*)d_in[6];  const float* bv  = (const float*)d_in[7];
    const float* Wpk = (const float*)d_in[8];  const float* bpk = (const float*)d_in[9];
    const float* Wpq = (const float*)d_in[10]; const float* bpq = (const float*)d_in[11];
    const float* Wo  = (const float*)d_in[12]; const float* bo  = (const float*)d_in[13];
    const float* lng = (const float*)d_in[14]; const float* lnb = (const float*)d_in[15];

    float *q_, *k_, *v_, *pk_, *pq_, *ctx_, *proj_;
    cudaGetSymbolAddress((void**)&q_, g_q);
    cudaGetSymbolAddress((void**)&k_, g_k);
    cudaGetSymbolAddress((void**)&v_, g_v);
    cudaGetSymbolAddress((void**)&pk_, g_pk);
    cudaGetSymbolAddress((void**)&pq_, g_pq);
    cudaGetSymbolAddress((void**)&ctx_, g_ctx);
    cudaGetSymbolAddress((void**)&proj_, g_proj);

    // smem: qS + kS (128*72) + bS (256*72) bf16 + Gs (128*132) f32 + Vt (64*136) bf16
    const int fused_smem = (128 * QSTR + 128 * QSTR + 256 * QSTR) * 2
                         + 128 * 132 * 4 + 64 * PSTR * 2;
    cudaFuncSetAttribute(attn_fused, cudaFuncAttributeMaxDynamicSharedMemorySize, fused_smem);

    gemm_bf16<<<dim3(8, 8, 3), 256>>>(hs, Wq, bq, q_, Wk, bk, k_, Wv, bv, v_);
    gemm_bf16<<<dim3(8, 16, 2), 256>>>(rel, Wpk, bpk, pk_, Wpq, bpq, pq_, Wpq, bpq, pq_);
    attn_fused<<<dim3(8, 16), 256, fused_smem>>>();
    gemm_bf16<<<dim3(8, 8, 1), 256>>>(ctx_, Wo, bo, proj_, Wo, bo, proj_, Wo, bo, proj_);
    ln_kernel<<<1024, 256>>>(hs, lng, lnb, (float*)d_out);
}